// round 1
// baseline (speedup 1.0000x reference)
#include <cuda_runtime.h>
#include <math.h>

#define T  16
#define NN 20000
#define EE 320000
#define CC 128
#define HH 128
#define PP 100000
#define TN (T*NN)
#define TE (T*EE)

// ---------------- device scratch (allowed: __device__ globals) ----------------
__device__ float g_hs[TN*HH];          // dinv-scaled GEMM output (gather source)
__device__ float g_layer[TN*HH];       // layer ping buffer
__device__ float g_feats[TN*HH];       // GCN stack output (GRU input)
__device__ float g_gi[(size_t)TN*3*HH];// precomputed input-gates for all steps
__device__ float g_gh[NN*3*HH];        // per-step hidden gates
__device__ float g_h[NN*HH];           // GRU hidden state
__device__ float g_dinv[TN];
__device__ int   g_cnt[TN];
__device__ int   g_cursor[TN];
__device__ int   g_rowptr[T*(NN+1)];
__device__ int   g_col[TE];

// ---------------- small utility kernels ----------------
__global__ void zero_int_kernel(int* p, int n) {
    int i = blockIdx.x*blockDim.x + threadIdx.x;
    if (i < n) p[i] = 0;
}
__global__ void zero_float_kernel(float* p, int n) {
    int i = blockIdx.x*blockDim.x + threadIdx.x;
    if (i < n) p[i] = 0.0f;
}

__global__ void count_kernel(const int* __restrict__ ei, int* __restrict__ cnt) {
    int i = blockIdx.x*blockDim.x + threadIdx.x;
    if (i >= TE) return;
    int t = i / EE, e = i - t*EE;
    int dst = ei[(size_t)t*2*EE + EE + e];
    atomicAdd(&cnt[t*NN + dst], 1);
}

__global__ void dinv_kernel(const int* __restrict__ cnt, float* __restrict__ dinv) {
    int i = blockIdx.x*blockDim.x + threadIdx.x;
    if (i >= TN) return;
    dinv[i] = rsqrtf((float)cnt[i] + 1.0f);
}

// per-frame exclusive scan of in-degree counts -> CSR row pointers
__global__ void scan_kernel(const int* __restrict__ cnt, int* __restrict__ rowptr) {
    int t = blockIdx.x;
    const int* c = cnt + t*NN;
    int* rp = rowptr + t*(NN+1);
    __shared__ int wsum[32];
    int lane = threadIdx.x & 31;
    int wid  = threadIdx.x >> 5;
    int carry = 0;
    for (int base = 0; base < NN; base += 1024) {
        int i = base + threadIdx.x;
        int v = (i < NN) ? c[i] : 0;
        int inc = v;
        #pragma unroll
        for (int o = 1; o < 32; o <<= 1) {
            int y = __shfl_up_sync(0xffffffffu, inc, o);
            if (lane >= o) inc += y;
        }
        if (lane == 31) wsum[wid] = inc;
        __syncthreads();
        if (wid == 0) {
            int s = wsum[lane];
            #pragma unroll
            for (int o = 1; o < 32; o <<= 1) {
                int y = __shfl_up_sync(0xffffffffu, s, o);
                if (lane >= o) s += y;
            }
            wsum[lane] = s;
        }
        __syncthreads();
        int woff = wid ? wsum[wid-1] : 0;
        if (i < NN) rp[i] = carry + woff + inc - v;
        carry += wsum[31];
        __syncthreads();
    }
    if (threadIdx.x == 0) rp[NN] = carry;
}

__global__ void scatter_kernel(const int* __restrict__ ei, const int* __restrict__ rowptr,
                               int* __restrict__ cursor, int* __restrict__ col) {
    int i = blockIdx.x*blockDim.x + threadIdx.x;
    if (i >= TE) return;
    int t = i / EE, e = i - t*EE;
    int src = ei[(size_t)t*2*EE + e];
    int dst = ei[(size_t)t*2*EE + EE + e];
    int pos = rowptr[t*(NN+1) + dst] + atomicAdd(&cursor[t*NN + dst], 1);
    col[(size_t)t*EE + pos] = src;
}

// ---------------- fp32x2 GEMM: C[M,128-colblock] = A[M,128] * B ----------------
// block tile 64 rows x 128 cols, 256 threads, 1 row x 32 cols per thread,
// accumulation via packed fma.rn.f32x2 (2x scalar FFMA throughput on sm_103a).
#define GEMM_AP 132
#define GEMM_SMEM ((64*GEMM_AP + 128*128)*4)

__device__ __forceinline__ void ffma2(unsigned long long &d, unsigned long long a, unsigned long long b) {
    asm("fma.rn.f32x2 %0, %1, %2, %0;" : "+l"(d) : "l"(a), "l"(b));
}

// EPI 0: out = acc * dinv[row]   (GCN layer GEMMs -> scaled message buffer)
// EPI 1: out = acc + bias[col]   (GRU gate GEMMs)
template<bool TRANSB, int EPI>
__global__ void __launch_bounds__(256, 2) gemm_kernel(
    const float* __restrict__ A, const float* __restrict__ B,
    const float* __restrict__ bias, const float* __restrict__ dinv,
    float* __restrict__ out, int M, int ldB, int ldOut)
{
    extern __shared__ float smem[];
    float* As = smem;                 // [64][GEMM_AP]
    float* Bs = smem + 64*GEMM_AP;    // [128][128]
    int tid  = threadIdx.x;
    int row0 = blockIdx.x * 64;
    int col0 = blockIdx.y * 128;

    if (!TRANSB) {
        for (int i = tid; i < 128*32; i += 256) {
            int k = i >> 5, c4 = (i & 31) * 4;
            float4 v = *(const float4*)&B[(size_t)k*ldB + col0 + c4];
            Bs[k*128+c4+0] = v.x; Bs[k*128+c4+1] = v.y;
            Bs[k*128+c4+2] = v.z; Bs[k*128+c4+3] = v.w;
        }
    } else {
        // B is [NCOLS,128] row-major; Bs[k][c] = B[col0+c][k]
        for (int i = tid; i < 128*32; i += 256) {
            int c = i >> 5, k4 = (i & 31) * 4;
            float4 v = *(const float4*)&B[(size_t)(col0 + c)*128 + k4];
            Bs[(k4+0)*128+c] = v.x; Bs[(k4+1)*128+c] = v.y;
            Bs[(k4+2)*128+c] = v.z; Bs[(k4+3)*128+c] = v.w;
        }
    }
    for (int i = tid; i < 64*32; i += 256) {
        int r = i >> 5, k4 = (i & 31) * 4;
        int grow = row0 + r;
        float4 v = make_float4(0.f,0.f,0.f,0.f);
        if (grow < M) v = *(const float4*)&A[(size_t)grow*128 + k4];
        As[r*GEMM_AP+k4+0] = v.x; As[r*GEMM_AP+k4+1] = v.y;
        As[r*GEMM_AP+k4+2] = v.z; As[r*GEMM_AP+k4+3] = v.w;
    }
    __syncthreads();

    int r  = tid >> 2;          // 0..63
    int cb = (tid & 3) * 32;    // 32-col slice

    unsigned long long acc[16];
    #pragma unroll
    for (int j = 0; j < 16; j++) acc[j] = 0ull;

    const float* arow = As + r*GEMM_AP;
    #pragma unroll 8
    for (int k = 0; k < 128; k++) {
        float a = arow[k];
        unsigned long long aa;
        asm("mov.b64 %0, {%1, %1};" : "=l"(aa) : "f"(a));
        const ulonglong2* brow = reinterpret_cast<const ulonglong2*>(Bs + k*128 + cb);
        #pragma unroll
        for (int j = 0; j < 8; j++) {
            ulonglong2 b = brow[j];
            ffma2(acc[2*j],   aa, b.x);
            ffma2(acc[2*j+1], aa, b.y);
        }
    }

    int row = row0 + r;
    if (row < M) {
        float scale = 1.0f;
        if (EPI == 0) scale = __ldg(&dinv[row]);
        float* orow = out + (size_t)row*ldOut + col0 + cb;
        #pragma unroll
        for (int j = 0; j < 8; j++) {
            union { unsigned long long u; float2 f; } c0, c1;
            c0.u = acc[2*j]; c1.u = acc[2*j+1];
            float4 o = make_float4(c0.f.x, c0.f.y, c1.f.x, c1.f.y);
            if (EPI == 0) { o.x*=scale; o.y*=scale; o.z*=scale; o.w*=scale; }
            else {
                float4 bb = *(const float4*)&bias[col0 + cb + j*4];
                o.x+=bb.x; o.y+=bb.y; o.z+=bb.z; o.w+=bb.w;
            }
            *(float4*)&orow[j*4] = o;
        }
    }
}

// ---------------- CSR gather aggregation: one warp per (frame, node) ----------------
template<bool RELU>
__global__ void agg_kernel(const float* __restrict__ hs, const float* __restrict__ dinv,
                           const int* __restrict__ rowptr, const int* __restrict__ col,
                           const float* __restrict__ bias, float* __restrict__ out)
{
    int g = blockIdx.x*blockDim.x + threadIdx.x;
    int w = g >> 5;
    if (w >= TN) return;
    int lane = g & 31;
    int t = w / NN, n = w - t*NN;
    const int* rp = rowptr + t*(NN+1);
    int beg = rp[n], end = rp[n+1];
    const int* cols = col + (size_t)t*EE;
    const float* hsf = hs + (size_t)t*NN*HH;
    int off = lane*4;
    float4 acc = *(const float4*)&hsf[n*HH + off];    // self-loop message
    int e = beg;
    for (; e + 4 <= end; e += 4) {
        int s0 = cols[e], s1 = cols[e+1], s2 = cols[e+2], s3 = cols[e+3];
        float4 v0 = *(const float4*)&hsf[s0*HH + off];
        float4 v1 = *(const float4*)&hsf[s1*HH + off];
        float4 v2 = *(const float4*)&hsf[s2*HH + off];
        float4 v3 = *(const float4*)&hsf[s3*HH + off];
        acc.x += (v0.x+v1.x)+(v2.x+v3.x);
        acc.y += (v0.y+v1.y)+(v2.y+v3.y);
        acc.z += (v0.z+v1.z)+(v2.z+v3.z);
        acc.w += (v0.w+v1.w)+(v2.w+v3.w);
    }
    for (; e < end; e++) {
        int s = cols[e];
        float4 v = *(const float4*)&hsf[s*HH + off];
        acc.x += v.x; acc.y += v.y; acc.z += v.z; acc.w += v.w;
    }
    float dv = dinv[w];
    float4 bb = *(const float4*)&bias[off];
    float4 o;
    o.x = fmaf(acc.x, dv, bb.x);
    o.y = fmaf(acc.y, dv, bb.y);
    o.z = fmaf(acc.z, dv, bb.z);
    o.w = fmaf(acc.w, dv, bb.w);
    if (RELU) {
        o.x = fmaxf(o.x, 0.f); o.y = fmaxf(o.y, 0.f);
        o.z = fmaxf(o.z, 0.f); o.w = fmaxf(o.w, 0.f);
    }
    *(float4*)&out[(size_t)w*HH + off] = o;
}

// ---------------- GRU gate fusion (in-place hidden update) ----------------
__global__ void gru_gates_kernel(const float* __restrict__ gi, const float* __restrict__ gh,
                                 float* __restrict__ h)
{
    int idx = blockIdx.x*blockDim.x + threadIdx.x;
    if (idx >= NN*HH/4) return;
    int n  = idx >> 5;          // H/4 == 32 vec4 per row
    int j4 = (idx & 31) * 4;
    const float* gir = gi + (size_t)n*384;
    const float* ghr = gh + (size_t)n*384;
    float4 ir  = *(const float4*)&gir[j4];
    float4 iz  = *(const float4*)&gir[128 + j4];
    float4 inn = *(const float4*)&gir[256 + j4];
    float4 hr  = *(const float4*)&ghr[j4];
    float4 hz  = *(const float4*)&ghr[128 + j4];
    float4 hn  = *(const float4*)&ghr[256 + j4];
    float4 hp  = *(const float4*)&h[(size_t)n*HH + j4];
    float4 o;
    #define GATE(c) { \
        float rr = 1.f/(1.f+__expf(-(ir.c + hr.c))); \
        float zz = 1.f/(1.f+__expf(-(iz.c + hz.c))); \
        float nn2 = tanhf(inn.c + rr*hn.c); \
        o.c = (1.f - zz)*nn2 + zz*hp.c; }
    GATE(x) GATE(y) GATE(z) GATE(w)
    #undef GATE
    *(float4*)&h[(size_t)n*HH + j4] = o;
}

// ---------------- pairwise dot decode: one warp per pair ----------------
__global__ void decode_kernel(const int* __restrict__ pairs, const float* __restrict__ h,
                              float* __restrict__ out)
{
    int g = blockIdx.x*blockDim.x + threadIdx.x;
    int w = g >> 5;
    if (w >= PP) return;
    int lane = g & 31;
    int s = pairs[w], d = pairs[PP + w];
    float4 a = *(const float4*)&h[(size_t)s*HH + lane*4];
    float4 b = *(const float4*)&h[(size_t)d*HH + lane*4];
    float sum = a.x*b.x + a.y*b.y + a.z*b.z + a.w*b.w;
    #pragma unroll
    for (int o = 16; o; o >>= 1) sum += __shfl_xor_sync(0xffffffffu, sum, o);
    if (lane == 0) out[w] = sum;
}

// ---------------- launch ----------------
extern "C" void kernel_launch(void* const* d_in, const int* in_sizes, int n_in,
                              void* d_out, int out_size)
{
    const float* x_seq = (const float*)d_in[0];
    const int*   ei    = (const int*)d_in[1];
    const int*   pairs = (const int*)d_in[2];
    const float* W1 = (const float*)d_in[3];
    const float* b1 = (const float*)d_in[4];
    const float* W2 = (const float*)d_in[5];
    const float* b2 = (const float*)d_in[6];
    const float* W3 = (const float*)d_in[7];
    const float* b3 = (const float*)d_in[8];
    const float* w_ih = (const float*)d_in[9];
    const float* w_hh = (const float*)d_in[10];
    const float* b_ih = (const float*)d_in[11];
    const float* b_hh = (const float*)d_in[12];
    float* out = (float*)d_out;
    (void)in_sizes; (void)n_in; (void)out_size;

    void* p;
    float *hs, *layer, *feats, *gi, *gh, *h, *dinv;
    int *cnt, *cursor, *rowptr, *col;
    cudaGetSymbolAddress(&p, g_hs);     hs     = (float*)p;
    cudaGetSymbolAddress(&p, g_layer);  layer  = (float*)p;
    cudaGetSymbolAddress(&p, g_feats);  feats  = (float*)p;
    cudaGetSymbolAddress(&p, g_gi);     gi     = (float*)p;
    cudaGetSymbolAddress(&p, g_gh);     gh     = (float*)p;
    cudaGetSymbolAddress(&p, g_h);      h      = (float*)p;
    cudaGetSymbolAddress(&p, g_dinv);   dinv   = (float*)p;
    cudaGetSymbolAddress(&p, g_cnt);    cnt    = (int*)p;
    cudaGetSymbolAddress(&p, g_cursor); cursor = (int*)p;
    cudaGetSymbolAddress(&p, g_rowptr); rowptr = (int*)p;
    cudaGetSymbolAddress(&p, g_col);    col    = (int*)p;

    cudaFuncSetAttribute(gemm_kernel<false,0>, cudaFuncAttributeMaxDynamicSharedMemorySize, GEMM_SMEM);
    cudaFuncSetAttribute(gemm_kernel<true,1>,  cudaFuncAttributeMaxDynamicSharedMemorySize, GEMM_SMEM);

    // ---- CSR build (all frames) ----
    zero_int_kernel<<<(TN+255)/256, 256>>>(cnt, TN);
    zero_int_kernel<<<(TN+255)/256, 256>>>(cursor, TN);
    zero_float_kernel<<<(NN*HH+255)/256, 256>>>(h, NN*HH);
    count_kernel<<<(TE+255)/256, 256>>>(ei, cnt);
    dinv_kernel<<<(TN+255)/256, 256>>>(cnt, dinv);
    scan_kernel<<<T, 1024>>>(cnt, rowptr);
    scatter_kernel<<<(TE+255)/256, 256>>>(ei, rowptr, cursor, col);

    // ---- 3 GCN layers, batched over all frames ----
    dim3 gL((TN+63)/64, 1);
    int aggBlocks = (TN*32 + 255)/256;
    gemm_kernel<false,0><<<gL, 256, GEMM_SMEM>>>(x_seq, W1, nullptr, dinv, hs, TN, HH, HH);
    agg_kernel<true ><<<aggBlocks, 256>>>(hs, dinv, rowptr, col, b1, layer);
    gemm_kernel<false,0><<<gL, 256, GEMM_SMEM>>>(layer, W2, nullptr, dinv, hs, TN, HH, HH);
    agg_kernel<true ><<<aggBlocks, 256>>>(hs, dinv, rowptr, col, b2, layer);
    gemm_kernel<false,0><<<gL, 256, GEMM_SMEM>>>(layer, W3, nullptr, dinv, hs, TN, HH, HH);
    agg_kernel<false><<<aggBlocks, 256>>>(hs, dinv, rowptr, col, b3, feats);

    // ---- GRU: batched input gates, then sequential hidden updates ----
    dim3 gGI((TN+63)/64, 3);
    gemm_kernel<true,1><<<gGI, 256, GEMM_SMEM>>>(feats, w_ih, b_ih, nullptr, gi, TN, 128, 384);

    dim3 gGH((NN+63)/64, 3);
    int gateBlocks = (NN*HH/4 + 255)/256;
    for (int t = 0; t < T; t++) {
        gemm_kernel<true,1><<<gGH, 256, GEMM_SMEM>>>(h, w_hh, b_hh, nullptr, gh, NN, 128, 384);
        gru_gates_kernel<<<gateBlocks, 256>>>(gi + (size_t)t*NN*3*HH, gh, h);
    }

    // ---- decode ----
    decode_kernel<<<(PP*32 + 255)/256, 256>>>(pairs, h, out);
}

// round 3
// speedup vs baseline: 5.4382x; 5.4382x over previous
#include <cuda_runtime.h>
#include <math.h>

#define T  16
#define NN 20000
#define EE 320000
#define CC 128
#define HH 128
#define PP 100000
#define TN (T*NN)
#define TE (T*EE)

// ---------------- device scratch ----------------
__device__ float g_hs[TN*HH];           // raw GEMM output h = x@W (gather source)
__device__ float g_layer[TN*HH];        // layer ping buffer
__device__ float g_feats[TN*HH];        // GCN output (GRU input)
__device__ float g_gi[(size_t)TN*3*HH]; // input gates, all steps
__device__ float g_gh[NN*3*HH];         // per-step hidden gates
__device__ float g_h[NN*HH];            // GRU hidden state
__device__ float g_dinv[TN];
__device__ float g_wihT[128*384];       // w_ih^T  [128][384]
__device__ float g_whhT[128*384];       // w_hh^T  [128][384]
__device__ int   g_cnt[TN];
__device__ int   g_cursor[TN];
__device__ int   g_rowptr[T*(NN+1)];
__device__ int   g_col[TE];

// ---------------- utility kernels ----------------
__global__ void zero_int_kernel(int* p, int n) {
    int i = blockIdx.x*blockDim.x + threadIdx.x;
    if (i < n) p[i] = 0;
}
__global__ void zero_float_kernel(float* p, int n) {
    int i = blockIdx.x*blockDim.x + threadIdx.x;
    if (i < n) p[i] = 0.0f;
}

__global__ void count_kernel(const int* __restrict__ ei, int* __restrict__ cnt) {
    int i = blockIdx.x*blockDim.x + threadIdx.x;
    if (i >= TE) return;
    int t = i / EE, e = i - t*EE;
    int dst = ei[(size_t)t*2*EE + EE + e];
    atomicAdd(&cnt[t*NN + dst], 1);
}

__global__ void dinv_kernel(const int* __restrict__ cnt, float* __restrict__ dinv) {
    int i = blockIdx.x*blockDim.x + threadIdx.x;
    if (i >= TN) return;
    dinv[i] = rsqrtf((float)cnt[i] + 1.0f);
}

// per-frame exclusive scan of in-degree counts -> CSR row pointers
__global__ void scan_kernel(const int* __restrict__ cnt, int* __restrict__ rowptr) {
    int t = blockIdx.x;
    const int* c = cnt + t*NN;
    int* rp = rowptr + t*(NN+1);
    __shared__ int wsum[32];
    int lane = threadIdx.x & 31;
    int wid  = threadIdx.x >> 5;
    int carry = 0;
    for (int base = 0; base < NN; base += 1024) {
        int i = base + threadIdx.x;
        int v = (i < NN) ? c[i] : 0;
        int inc = v;
        #pragma unroll
        for (int o = 1; o < 32; o <<= 1) {
            int y = __shfl_up_sync(0xffffffffu, inc, o);
            if (lane >= o) inc += y;
        }
        if (lane == 31) wsum[wid] = inc;
        __syncthreads();
        if (wid == 0) {
            int s = wsum[lane];
            #pragma unroll
            for (int o = 1; o < 32; o <<= 1) {
                int y = __shfl_up_sync(0xffffffffu, s, o);
                if (lane >= o) s += y;
            }
            wsum[lane] = s;
        }
        __syncthreads();
        int woff = wid ? wsum[wid-1] : 0;
        if (i < NN) rp[i] = carry + woff + inc - v;
        carry += wsum[31];
        __syncthreads();
    }
    if (threadIdx.x == 0) rp[NN] = carry;
}

__global__ void scatter_kernel(const int* __restrict__ ei, const int* __restrict__ rowptr,
                               int* __restrict__ cursor, int* __restrict__ col) {
    int i = blockIdx.x*blockDim.x + threadIdx.x;
    if (i >= TE) return;
    int t = i / EE, e = i - t*EE;
    int src = ei[(size_t)t*2*EE + e];
    int dst = ei[(size_t)t*2*EE + EE + e];
    int pos = rowptr[t*(NN+1) + dst] + atomicAdd(&cursor[t*NN + dst], 1);
    col[(size_t)t*EE + pos] = src;
}

// transpose [384][128] -> [128][384]
__global__ void transpose_kernel(const float* __restrict__ in, float* __restrict__ outT) {
    int i = blockIdx.x*blockDim.x + threadIdx.x;
    if (i >= 384*128) return;
    int k = i & 127, j = i >> 7;          // in[j][k], read coalesced
    outT[k*384 + j] = in[i];
}

// ---------------- fp32x2 GEMM: C[128-rowblock, 128-colblock] = A[M,128] * B ----------------
// 256 threads, micro-tile 4 rows (strided 32) x 16 cols (4 chunks of 4, strided 32).
// Conflict-free shared loads: A banks = 4*tr + k (4 distinct, bcast 8);
//                             B banks = 4*tc (8 distinct 16B reqs = 1 phase).
#define AS_LD 132
#define GEMM_SMEM ((128*AS_LD + 128*128)*4)

__device__ __forceinline__ void ffma2(unsigned long long &d, unsigned long long a, unsigned long long b) {
    asm("fma.rn.f32x2 %0, %1, %2, %0;" : "+l"(d) : "l"(a), "l"(b));
}

// EPI 0: out = acc            (GCN layer GEMMs -> raw h)
// EPI 1: out = acc + bias[col](GRU gate GEMMs)
template<int EPI>
__global__ void __launch_bounds__(256, 1) gemm_kernel(
    const float* __restrict__ A, const float* __restrict__ B,
    const float* __restrict__ bias,
    float* __restrict__ out, int M, int ldB, int ldOut)
{
    extern __shared__ float smem[];
    float* As = smem;                  // [128][AS_LD]
    float* Bs = smem + 128*AS_LD;      // [128][128]
    int tid  = threadIdx.x;
    int row0 = blockIdx.x * 128;
    int col0 = blockIdx.y * 128;

    // stage B (row-major, coalesced LDG + conflict-free STS.128)
    for (int i = tid; i < 128*32; i += 256) {
        int k = i >> 5, c4 = (i & 31) * 4;
        float4 v = *(const float4*)&B[(size_t)k*ldB + col0 + c4];
        *(float4*)&Bs[k*128 + c4] = v;
    }
    // stage A (row-major pad-132)
    for (int i = tid; i < 128*32; i += 256) {
        int r = i >> 5, k4 = (i & 31) * 4;
        int grow = row0 + r;
        float4 v = make_float4(0.f,0.f,0.f,0.f);
        if (grow < M) v = *(const float4*)&A[(size_t)grow*128 + k4];
        *(float4*)&As[r*AS_LD + k4] = v;
    }
    __syncthreads();

    int tr = tid >> 3;   // 0..31 -> rows tr + 32*rr
    int tc = tid & 7;    // 0..7  -> cols tc*4 + 32*m

    unsigned long long acc[4][8];
    #pragma unroll
    for (int rr = 0; rr < 4; rr++)
        #pragma unroll
        for (int j = 0; j < 8; j++) acc[rr][j] = 0ull;

    #pragma unroll 4
    for (int k = 0; k < 128; k++) {
        unsigned long long aa[4];
        #pragma unroll
        for (int rr = 0; rr < 4; rr++) {
            float a = As[(tr + 32*rr)*AS_LD + k];
            asm("mov.b64 %0, {%1, %1};" : "=l"(aa[rr]) : "f"(a));
        }
        #pragma unroll
        for (int m = 0; m < 4; m++) {
            ulonglong2 b = *(const ulonglong2*)&Bs[k*128 + m*32 + tc*4];
            #pragma unroll
            for (int rr = 0; rr < 4; rr++) {
                ffma2(acc[rr][2*m],   aa[rr], b.x);
                ffma2(acc[rr][2*m+1], aa[rr], b.y);
            }
        }
    }

    #pragma unroll
    for (int rr = 0; rr < 4; rr++) {
        int row = row0 + tr + 32*rr;
        if (row >= M) continue;
        float* orow = out + (size_t)row*ldOut + col0;
        #pragma unroll
        for (int m = 0; m < 4; m++) {
            union { unsigned long long u; float2 f; } lo, hi;
            lo.u = acc[rr][2*m]; hi.u = acc[rr][2*m+1];
            float4 o = make_float4(lo.f.x, lo.f.y, hi.f.x, hi.f.y);
            if (EPI == 1) {
                float4 bb = *(const float4*)&bias[col0 + m*32 + tc*4];
                o.x += bb.x; o.y += bb.y; o.z += bb.z; o.w += bb.w;
            }
            *(float4*)&orow[m*32 + tc*4] = o;
        }
    }
}

// ---------------- CSR gather aggregation: one warp per (frame, node) ----------------
// hs holds RAW h = x@W; per-edge scaling by dinv[src] done here.
template<bool RELU>
__global__ void agg_kernel(const float* __restrict__ hs, const float* __restrict__ dinv,
                           const int* __restrict__ rowptr, const int* __restrict__ col,
                           const float* __restrict__ bias, float* __restrict__ out)
{
    int g = blockIdx.x*blockDim.x + threadIdx.x;
    int w = g >> 5;
    if (w >= TN) return;
    int lane = g & 31;
    int t = w / NN, n = w - t*NN;
    const int* rp = rowptr + t*(NN+1);
    int beg = rp[n], end = rp[n+1];
    const int* cols = col + (size_t)t*EE;
    const float* hsf = hs + (size_t)t*NN*HH;
    const float* dvf = dinv + t*NN;
    int off = lane*4;
    float dv = dvf[n];
    float4 hn = *(const float4*)&hsf[n*HH + off];
    float4 acc = make_float4(hn.x*dv, hn.y*dv, hn.z*dv, hn.w*dv);  // dinv[n]*h[n]
    int e = beg;
    for (; e + 4 <= end; e += 4) {
        int s0 = cols[e], s1 = cols[e+1], s2 = cols[e+2], s3 = cols[e+3];
        float d0 = dvf[s0], d1 = dvf[s1], d2 = dvf[s2], d3 = dvf[s3];
        float4 v0 = *(const float4*)&hsf[s0*HH + off];
        float4 v1 = *(const float4*)&hsf[s1*HH + off];
        float4 v2 = *(const float4*)&hsf[s2*HH + off];
        float4 v3 = *(const float4*)&hsf[s3*HH + off];
        acc.x = fmaf(v0.x,d0, fmaf(v1.x,d1, fmaf(v2.x,d2, fmaf(v3.x,d3, acc.x))));
        acc.y = fmaf(v0.y,d0, fmaf(v1.y,d1, fmaf(v2.y,d2, fmaf(v3.y,d3, acc.y))));
        acc.z = fmaf(v0.z,d0, fmaf(v1.z,d1, fmaf(v2.z,d2, fmaf(v3.z,d3, acc.z))));
        acc.w = fmaf(v0.w,d0, fmaf(v1.w,d1, fmaf(v2.w,d2, fmaf(v3.w,d3, acc.w))));
    }
    for (; e < end; e++) {
        int s = cols[e];
        float ds = dvf[s];
        float4 v = *(const float4*)&hsf[s*HH + off];
        acc.x = fmaf(v.x, ds, acc.x); acc.y = fmaf(v.y, ds, acc.y);
        acc.z = fmaf(v.z, ds, acc.z); acc.w = fmaf(v.w, ds, acc.w);
    }
    float4 bb = *(const float4*)&bias[off];
    float4 o;
    o.x = fmaf(acc.x, dv, bb.x);
    o.y = fmaf(acc.y, dv, bb.y);
    o.z = fmaf(acc.z, dv, bb.z);
    o.w = fmaf(acc.w, dv, bb.w);
    if (RELU) {
        o.x = fmaxf(o.x, 0.f); o.y = fmaxf(o.y, 0.f);
        o.z = fmaxf(o.z, 0.f); o.w = fmaxf(o.w, 0.f);
    }
    *(float4*)&out[(size_t)w*HH + off] = o;
}

// ---------------- GRU gate fusion ----------------
__global__ void gru_gates_kernel(const float* __restrict__ gi, const float* __restrict__ gh,
                                 float* __restrict__ h)
{
    int idx = blockIdx.x*blockDim.x + threadIdx.x;
    if (idx >= NN*HH/4) return;
    int n  = idx >> 5;
    int j4 = (idx & 31) * 4;
    const float* gir = gi + (size_t)n*384;
    const float* ghr = gh + (size_t)n*384;
    float4 ir  = *(const float4*)&gir[j4];
    float4 iz  = *(const float4*)&gir[128 + j4];
    float4 inn = *(const float4*)&gir[256 + j4];
    float4 hr  = *(const float4*)&ghr[j4];
    float4 hz  = *(const float4*)&ghr[128 + j4];
    float4 hn  = *(const float4*)&ghr[256 + j4];
    float4 hp  = *(const float4*)&h[(size_t)n*HH + j4];
    float4 o;
    #define GATE(c) { \
        float rr = 1.f/(1.f+__expf(-(ir.c + hr.c))); \
        float zz = 1.f/(1.f+__expf(-(iz.c + hz.c))); \
        float nn2 = tanhf(inn.c + rr*hn.c); \
        o.c = (1.f - zz)*nn2 + zz*hp.c; }
    GATE(x) GATE(y) GATE(z) GATE(w)
    #undef GATE
    *(float4*)&h[(size_t)n*HH + j4] = o;
}

// ---------------- decode ----------------
__global__ void decode_kernel(const int* __restrict__ pairs, const float* __restrict__ h,
                              float* __restrict__ out)
{
    int g = blockIdx.x*blockDim.x + threadIdx.x;
    int w = g >> 5;
    if (w >= PP) return;
    int lane = g & 31;
    int s = pairs[w], d = pairs[PP + w];
    float4 a = *(const float4*)&h[(size_t)s*HH + lane*4];
    float4 b = *(const float4*)&h[(size_t)d*HH + lane*4];
    float sum = a.x*b.x + a.y*b.y + a.z*b.z + a.w*b.w;
    #pragma unroll
    for (int o = 16; o; o >>= 1) sum += __shfl_xor_sync(0xffffffffu, sum, o);
    if (lane == 0) out[w] = sum;
}

// ---------------- launch ----------------
extern "C" void kernel_launch(void* const* d_in, const int* in_sizes, int n_in,
                              void* d_out, int out_size)
{
    const float* x_seq = (const float*)d_in[0];
    const int*   ei    = (const int*)d_in[1];
    const int*   pairs = (const int*)d_in[2];
    const float* W1 = (const float*)d_in[3];
    const float* b1 = (const float*)d_in[4];
    const float* W2 = (const float*)d_in[5];
    const float* b2 = (const float*)d_in[6];
    const float* W3 = (const float*)d_in[7];
    const float* b3 = (const float*)d_in[8];
    const float* w_ih = (const float*)d_in[9];
    const float* w_hh = (const float*)d_in[10];
    const float* b_ih = (const float*)d_in[11];
    const float* b_hh = (const float*)d_in[12];
    float* out = (float*)d_out;
    (void)in_sizes; (void)n_in; (void)out_size;

    void* p;
    float *hs, *layer, *feats, *gi, *gh, *h, *dinv, *wihT, *whhT;
    int *cnt, *cursor, *rowptr, *col;
    cudaGetSymbolAddress(&p, g_hs);     hs     = (float*)p;
    cudaGetSymbolAddress(&p, g_layer);  layer  = (float*)p;
    cudaGetSymbolAddress(&p, g_feats);  feats  = (float*)p;
    cudaGetSymbolAddress(&p, g_gi);     gi     = (float*)p;
    cudaGetSymbolAddress(&p, g_gh);     gh     = (float*)p;
    cudaGetSymbolAddress(&p, g_h);      h      = (float*)p;
    cudaGetSymbolAddress(&p, g_dinv);   dinv   = (float*)p;
    cudaGetSymbolAddress(&p, g_wihT);   wihT   = (float*)p;
    cudaGetSymbolAddress(&p, g_whhT);   whhT   = (float*)p;
    cudaGetSymbolAddress(&p, g_cnt);    cnt    = (int*)p;
    cudaGetSymbolAddress(&p, g_cursor); cursor = (int*)p;
    cudaGetSymbolAddress(&p, g_rowptr); rowptr = (int*)p;
    cudaGetSymbolAddress(&p, g_col);    col    = (int*)p;

    cudaFuncSetAttribute(gemm_kernel<0>, cudaFuncAttributeMaxDynamicSharedMemorySize, GEMM_SMEM);
    cudaFuncSetAttribute(gemm_kernel<1>, cudaFuncAttributeMaxDynamicSharedMemorySize, GEMM_SMEM);

    // idx 0..2: zeroing
    zero_int_kernel<<<(TN+255)/256, 256>>>(cnt, TN);
    zero_int_kernel<<<(TN+255)/256, 256>>>(cursor, TN);
    zero_float_kernel<<<(NN*HH+255)/256, 256>>>(h, NN*HH);

    // idx 3: first big GEMM (placed here for ncu -s profiling window)
    dim3 gL(TN/128, 1);
    gemm_kernel<0><<<gL, 256, GEMM_SMEM>>>(x_seq, W1, nullptr, hs, TN, 128, 128);

    // idx 4..9: CSR build + weight transposes
    count_kernel<<<(TE+255)/256, 256>>>(ei, cnt);
    dinv_kernel<<<(TN+255)/256, 256>>>(cnt, dinv);
    scan_kernel<<<T, 1024>>>(cnt, rowptr);
    scatter_kernel<<<(TE+255)/256, 256>>>(ei, rowptr, cursor, col);
    transpose_kernel<<<(384*128+255)/256, 256>>>(w_ih, wihT);
    transpose_kernel<<<(384*128+255)/256, 256>>>(w_hh, whhT);

    // GCN layers
    int aggBlocks = (TN*32 + 255)/256;
    agg_kernel<true ><<<aggBlocks, 256>>>(hs, dinv, rowptr, col, b1, layer);
    gemm_kernel<0><<<gL, 256, GEMM_SMEM>>>(layer, W2, nullptr, hs, TN, 128, 128);
    agg_kernel<true ><<<aggBlocks, 256>>>(hs, dinv, rowptr, col, b2, layer);
    gemm_kernel<0><<<gL, 256, GEMM_SMEM>>>(layer, W3, nullptr, hs, TN, 128, 128);
    agg_kernel<false><<<aggBlocks, 256>>>(hs, dinv, rowptr, col, b3, feats);

    // GRU: batched input gates, sequential hidden chain
    dim3 gGI(TN/128, 3);
    gemm_kernel<1><<<gGI, 256, GEMM_SMEM>>>(feats, wihT, b_ih, gi, TN, 384, 384);

    dim3 gGH((NN+127)/128, 3);
    int gateBlocks = (NN*HH/4 + 255)/256;
    for (int t = 0; t < T; t++) {
        gemm_kernel<1><<<gGH, 256, GEMM_SMEM>>>(h, whhT, b_hh, gh, NN, 384, 384);
        gru_gates_kernel<<<gateBlocks, 256>>>(gi + (size_t)t*NN*3*HH, gh, h);
    }

    decode_kernel<<<(PP*32 + 255)/256, 256>>>(pairs, h, out);
}

// round 4
// speedup vs baseline: 7.3118x; 1.3445x over previous
#include <cuda_runtime.h>
#include <math.h>

#define T  16
#define NN 20000
#define EE 320000
#define CC 128
#define HH 128
#define PP 100000
#define TN (T*NN)
#define TE (T*EE)

// ---------------- device scratch ----------------
__device__ float g_hs[TN*HH];           // raw GEMM output h = x@W (gather source)
__device__ float g_layer[TN*HH];        // layer ping buffer
__device__ float g_feats[TN*HH];        // GCN output (GRU input)
__device__ float g_gi[(size_t)TN*3*HH]; // input gates, all steps
__device__ float g_gh[NN*3*HH];         // per-step hidden gates
__device__ float g_h[NN*HH];            // GRU hidden state
__device__ float g_dinv[TN];
__device__ float g_wihT[128*384];       // w_ih^T  [128][384]
__device__ float g_whhT[128*384];       // w_hh^T  [128][384]
__device__ int   g_cnt[TN];
__device__ int   g_cursor[TN];
__device__ int   g_rowptr[T*(NN+1)];
__device__ int   g_col[TE];

// ---------------- utility kernels ----------------
__global__ void zero_int_kernel(int* p, int n) {
    int i = blockIdx.x*blockDim.x + threadIdx.x;
    if (i < n) p[i] = 0;
}
__global__ void zero_float_kernel(float* p, int n) {
    int i = blockIdx.x*blockDim.x + threadIdx.x;
    if (i < n) p[i] = 0.0f;
}

__global__ void count_kernel(const int* __restrict__ ei, int* __restrict__ cnt) {
    int i = blockIdx.x*blockDim.x + threadIdx.x;
    if (i >= TE) return;
    int t = i / EE, e = i - t*EE;
    int dst = ei[(size_t)t*2*EE + EE + e];
    atomicAdd(&cnt[t*NN + dst], 1);
}

__global__ void dinv_kernel(const int* __restrict__ cnt, float* __restrict__ dinv) {
    int i = blockIdx.x*blockDim.x + threadIdx.x;
    if (i >= TN) return;
    dinv[i] = rsqrtf((float)cnt[i] + 1.0f);
}

// per-frame exclusive scan of in-degree counts -> CSR row pointers
__global__ void scan_kernel(const int* __restrict__ cnt, int* __restrict__ rowptr) {
    int t = blockIdx.x;
    const int* c = cnt + t*NN;
    int* rp = rowptr + t*(NN+1);
    __shared__ int wsum[32];
    int lane = threadIdx.x & 31;
    int wid  = threadIdx.x >> 5;
    int carry = 0;
    for (int base = 0; base < NN; base += 1024) {
        int i = base + threadIdx.x;
        int v = (i < NN) ? c[i] : 0;
        int inc = v;
        #pragma unroll
        for (int o = 1; o < 32; o <<= 1) {
            int y = __shfl_up_sync(0xffffffffu, inc, o);
            if (lane >= o) inc += y;
        }
        if (lane == 31) wsum[wid] = inc;
        __syncthreads();
        if (wid == 0) {
            int s = wsum[lane];
            #pragma unroll
            for (int o = 1; o < 32; o <<= 1) {
                int y = __shfl_up_sync(0xffffffffu, s, o);
                if (lane >= o) s += y;
            }
            wsum[lane] = s;
        }
        __syncthreads();
        int woff = wid ? wsum[wid-1] : 0;
        if (i < NN) rp[i] = carry + woff + inc - v;
        carry += wsum[31];
        __syncthreads();
    }
    if (threadIdx.x == 0) rp[NN] = carry;
}

__global__ void scatter_kernel(const int* __restrict__ ei, const int* __restrict__ rowptr,
                               int* __restrict__ cursor, int* __restrict__ col) {
    int i = blockIdx.x*blockDim.x + threadIdx.x;
    if (i >= TE) return;
    int t = i / EE, e = i - t*EE;
    int src = ei[(size_t)t*2*EE + e];
    int dst = ei[(size_t)t*2*EE + EE + e];
    int pos = rowptr[t*(NN+1) + dst] + atomicAdd(&cursor[t*NN + dst], 1);
    col[(size_t)t*EE + pos] = src;
}

// transpose [384][128] -> [128][384]
__global__ void transpose_kernel(const float* __restrict__ in, float* __restrict__ outT) {
    int i = blockIdx.x*blockDim.x + threadIdx.x;
    if (i >= 384*128) return;
    int k = i & 127, j = i >> 7;
    outT[k*384 + j] = in[i];
}

// ---------------- fp32x2 GEMM v2 ----------------
// 128x128 tile, K=128 in 4 double-buffered chunks of 32.
// smem = Bs[128][128] + As[2][32][129] = 96.3 KB -> 2 blocks/SM (16 warps).
// Global A prefetched to regs during compute; all LDS conflict-free.
#define BK   32
#define A_LD 129
#define GEMM_SMEM ((128*128 + 2*BK*A_LD)*4)

__device__ __forceinline__ void ffma2(unsigned long long &d, unsigned long long a, unsigned long long b) {
    asm("fma.rn.f32x2 %0, %1, %2, %0;" : "+l"(d) : "l"(a), "l"(b));
}

// EPI 0: out = acc            (GCN layer GEMMs)
// EPI 1: out = acc + bias[col](GRU gate GEMMs)
template<int EPI>
__global__ void __launch_bounds__(256, 2) gemm_kernel(
    const float* __restrict__ A, const float* __restrict__ B,
    const float* __restrict__ bias,
    float* __restrict__ out, int M, int ldB, int ldOut)
{
    extern __shared__ float smem[];
    float* Bs = smem;                 // [128][128]
    float* As = smem + 128*128;       // [2][BK][A_LD], layout As[k][row]
    int tid  = threadIdx.x;
    int row0 = blockIdx.x * 128;
    int col0 = blockIdx.y * 128;

    int ar  = tid >> 3;        // 0..31 (A staging row within 32-group)
    int ak4 = (tid & 7) * 4;   // 0..28 (A staging k4)

    // stage full B panel: coalesced LDG.128 + conflict-free STS.128
    for (int i = tid; i < 128*32; i += 256) {
        int k = i >> 5, c4 = (i & 31) * 4;
        *(float4*)&Bs[k*128 + c4] = *(const float4*)&B[(size_t)k*ldB + col0 + c4];
    }

    // stage A chunk 0 (transposed: As[k][row], pad 129 -> banks (k+row)%32)
    float4 v[4];
    #pragma unroll
    for (int it = 0; it < 4; it++) {
        int grow = row0 + ar + 32*it;
        v[it] = (grow < M) ? *(const float4*)&A[(size_t)grow*128 + ak4]
                           : make_float4(0.f,0.f,0.f,0.f);
    }
    #pragma unroll
    for (int it = 0; it < 4; it++) {
        int r = ar + 32*it;
        As[(ak4+0)*A_LD + r] = v[it].x;
        As[(ak4+1)*A_LD + r] = v[it].y;
        As[(ak4+2)*A_LD + r] = v[it].z;
        As[(ak4+3)*A_LD + r] = v[it].w;
    }
    __syncthreads();

    int tr = tid >> 3;   // rows tr + 32*rr
    int tc = tid & 7;    // cols tc*4 + 32*m

    unsigned long long acc[4][8];
    #pragma unroll
    for (int rr = 0; rr < 4; rr++)
        #pragma unroll
        for (int j = 0; j < 8; j++) acc[rr][j] = 0ull;

    #pragma unroll
    for (int c = 0; c < 4; c++) {
        // prefetch next A chunk from global into registers
        if (c < 3) {
            #pragma unroll
            for (int it = 0; it < 4; it++) {
                int grow = row0 + ar + 32*it;
                v[it] = (grow < M) ? *(const float4*)&A[(size_t)grow*128 + (c+1)*BK + ak4]
                                   : make_float4(0.f,0.f,0.f,0.f);
            }
        }
        const float* Ac = As + (c & 1)*BK*A_LD;
        const float* Bc = Bs + c*BK*128;
        #pragma unroll 8
        for (int kk = 0; kk < BK; kk++) {
            unsigned long long aa[4];
            #pragma unroll
            for (int rr = 0; rr < 4; rr++) {
                float a = Ac[kk*A_LD + tr + 32*rr];
                asm("mov.b64 %0, {%1, %1};" : "=l"(aa[rr]) : "f"(a));
            }
            #pragma unroll
            for (int m = 0; m < 4; m++) {
                ulonglong2 b = *(const ulonglong2*)&Bc[kk*128 + m*32 + tc*4];
                #pragma unroll
                for (int rr = 0; rr < 4; rr++) {
                    ffma2(acc[rr][2*m],   aa[rr], b.x);
                    ffma2(acc[rr][2*m+1], aa[rr], b.y);
                }
            }
        }
        if (c < 3) {
            float* An = As + ((c+1) & 1)*BK*A_LD;
            #pragma unroll
            for (int it = 0; it < 4; it++) {
                int r = ar + 32*it;
                An[(ak4+0)*A_LD + r] = v[it].x;
                An[(ak4+1)*A_LD + r] = v[it].y;
                An[(ak4+2)*A_LD + r] = v[it].z;
                An[(ak4+3)*A_LD + r] = v[it].w;
            }
            __syncthreads();
        }
    }

    #pragma unroll
    for (int rr = 0; rr < 4; rr++) {
        int row = row0 + tr + 32*rr;
        if (row >= M) continue;
        float* orow = out + (size_t)row*ldOut + col0;
        #pragma unroll
        for (int m = 0; m < 4; m++) {
            union { unsigned long long u; float2 f; } lo, hi;
            lo.u = acc[rr][2*m]; hi.u = acc[rr][2*m+1];
            float4 o = make_float4(lo.f.x, lo.f.y, hi.f.x, hi.f.y);
            if (EPI == 1) {
                float4 bb = *(const float4*)&bias[col0 + m*32 + tc*4];
                o.x += bb.x; o.y += bb.y; o.z += bb.z; o.w += bb.w;
            }
            *(float4*)&orow[m*32 + tc*4] = o;
        }
    }
}

// ---------------- CSR gather aggregation: one warp per (frame, node) ----------------
template<bool RELU>
__global__ void agg_kernel(const float* __restrict__ hs, const float* __restrict__ dinv,
                           const int* __restrict__ rowptr, const int* __restrict__ col,
                           const float* __restrict__ bias, float* __restrict__ out)
{
    int g = blockIdx.x*blockDim.x + threadIdx.x;
    int w = g >> 5;
    if (w >= TN) return;
    int lane = g & 31;
    int t = w / NN, n = w - t*NN;
    const int* rp = rowptr + t*(NN+1);
    int beg = rp[n], end = rp[n+1];
    const int* cols = col + (size_t)t*EE;
    const float* hsf = hs + (size_t)t*NN*HH;
    const float* dvf = dinv + t*NN;
    int off = lane*4;
    float dv = dvf[n];
    float4 hn = *(const float4*)&hsf[n*HH + off];
    float4 acc = make_float4(hn.x*dv, hn.y*dv, hn.z*dv, hn.w*dv);
    int e = beg;
    for (; e + 4 <= end; e += 4) {
        int s0 = cols[e], s1 = cols[e+1], s2 = cols[e+2], s3 = cols[e+3];
        float d0 = dvf[s0], d1 = dvf[s1], d2 = dvf[s2], d3 = dvf[s3];
        float4 v0 = *(const float4*)&hsf[s0*HH + off];
        float4 v1 = *(const float4*)&hsf[s1*HH + off];
        float4 v2 = *(const float4*)&hsf[s2*HH + off];
        float4 v3 = *(const float4*)&hsf[s3*HH + off];
        acc.x = fmaf(v0.x,d0, fmaf(v1.x,d1, fmaf(v2.x,d2, fmaf(v3.x,d3, acc.x))));
        acc.y = fmaf(v0.y,d0, fmaf(v1.y,d1, fmaf(v2.y,d2, fmaf(v3.y,d3, acc.y))));
        acc.z = fmaf(v0.z,d0, fmaf(v1.z,d1, fmaf(v2.z,d2, fmaf(v3.z,d3, acc.z))));
        acc.w = fmaf(v0.w,d0, fmaf(v1.w,d1, fmaf(v2.w,d2, fmaf(v3.w,d3, acc.w))));
    }
    for (; e < end; e++) {
        int s = cols[e];
        float ds = dvf[s];
        float4 vv = *(const float4*)&hsf[s*HH + off];
        acc.x = fmaf(vv.x, ds, acc.x); acc.y = fmaf(vv.y, ds, acc.y);
        acc.z = fmaf(vv.z, ds, acc.z); acc.w = fmaf(vv.w, ds, acc.w);
    }
    float4 bb = *(const float4*)&bias[off];
    float4 o;
    o.x = fmaf(acc.x, dv, bb.x);
    o.y = fmaf(acc.y, dv, bb.y);
    o.z = fmaf(acc.z, dv, bb.z);
    o.w = fmaf(acc.w, dv, bb.w);
    if (RELU) {
        o.x = fmaxf(o.x, 0.f); o.y = fmaxf(o.y, 0.f);
        o.z = fmaxf(o.z, 0.f); o.w = fmaxf(o.w, 0.f);
    }
    *(float4*)&out[(size_t)w*HH + off] = o;
}

// ---------------- GRU gate fusion ----------------
__global__ void gru_gates_kernel(const float* __restrict__ gi, const float* __restrict__ gh,
                                 float* __restrict__ h)
{
    int idx = blockIdx.x*blockDim.x + threadIdx.x;
    if (idx >= NN*HH/4) return;
    int n  = idx >> 5;
    int j4 = (idx & 31) * 4;
    const float* gir = gi + (size_t)n*384;
    const float* ghr = gh + (size_t)n*384;
    float4 ir  = *(const float4*)&gir[j4];
    float4 iz  = *(const float4*)&gir[128 + j4];
    float4 inn = *(const float4*)&gir[256 + j4];
    float4 hr  = *(const float4*)&ghr[j4];
    float4 hz  = *(const float4*)&ghr[128 + j4];
    float4 hn  = *(const float4*)&ghr[256 + j4];
    float4 hp  = *(const float4*)&h[(size_t)n*HH + j4];
    float4 o;
    #define GATE(c) { \
        float rr = 1.f/(1.f+__expf(-(ir.c + hr.c))); \
        float zz = 1.f/(1.f+__expf(-(iz.c + hz.c))); \
        float nn2 = tanhf(inn.c + rr*hn.c); \
        o.c = (1.f - zz)*nn2 + zz*hp.c; }
    GATE(x) GATE(y) GATE(z) GATE(w)
    #undef GATE
    *(float4*)&h[(size_t)n*HH + j4] = o;
}

// ---------------- decode ----------------
__global__ void decode_kernel(const int* __restrict__ pairs, const float* __restrict__ h,
                              float* __restrict__ out)
{
    int g = blockIdx.x*blockDim.x + threadIdx.x;
    int w = g >> 5;
    if (w >= PP) return;
    int lane = g & 31;
    int s = pairs[w], d = pairs[PP + w];
    float4 a = *(const float4*)&h[(size_t)s*HH + lane*4];
    float4 b = *(const float4*)&h[(size_t)d*HH + lane*4];
    float sum = a.x*b.x + a.y*b.y + a.z*b.z + a.w*b.w;
    #pragma unroll
    for (int o = 16; o; o >>= 1) sum += __shfl_xor_sync(0xffffffffu, sum, o);
    if (lane == 0) out[w] = sum;
}

// ---------------- launch ----------------
extern "C" void kernel_launch(void* const* d_in, const int* in_sizes, int n_in,
                              void* d_out, int out_size)
{
    const float* x_seq = (const float*)d_in[0];
    const int*   ei    = (const int*)d_in[1];
    const int*   pairs = (const int*)d_in[2];
    const float* W1 = (const float*)d_in[3];
    const float* b1 = (const float*)d_in[4];
    const float* W2 = (const float*)d_in[5];
    const float* b2 = (const float*)d_in[6];
    const float* W3 = (const float*)d_in[7];
    const float* b3 = (const float*)d_in[8];
    const float* w_ih = (const float*)d_in[9];
    const float* w_hh = (const float*)d_in[10];
    const float* b_ih = (const float*)d_in[11];
    const float* b_hh = (const float*)d_in[12];
    float* out = (float*)d_out;
    (void)in_sizes; (void)n_in; (void)out_size;

    void* p;
    float *hs, *layer, *feats, *gi, *gh, *h, *dinv, *wihT, *whhT;
    int *cnt, *cursor, *rowptr, *col;
    cudaGetSymbolAddress(&p, g_hs);     hs     = (float*)p;
    cudaGetSymbolAddress(&p, g_layer);  layer  = (float*)p;
    cudaGetSymbolAddress(&p, g_feats);  feats  = (float*)p;
    cudaGetSymbolAddress(&p, g_gi);     gi     = (float*)p;
    cudaGetSymbolAddress(&p, g_gh);     gh     = (float*)p;
    cudaGetSymbolAddress(&p, g_h);      h      = (float*)p;
    cudaGetSymbolAddress(&p, g_dinv);   dinv   = (float*)p;
    cudaGetSymbolAddress(&p, g_wihT);   wihT   = (float*)p;
    cudaGetSymbolAddress(&p, g_whhT);   whhT   = (float*)p;
    cudaGetSymbolAddress(&p, g_cnt);    cnt    = (int*)p;
    cudaGetSymbolAddress(&p, g_cursor); cursor = (int*)p;
    cudaGetSymbolAddress(&p, g_rowptr); rowptr = (int*)p;
    cudaGetSymbolAddress(&p, g_col);    col    = (int*)p;

    cudaFuncSetAttribute(gemm_kernel<0>, cudaFuncAttributeMaxDynamicSharedMemorySize, GEMM_SMEM);
    cudaFuncSetAttribute(gemm_kernel<1>, cudaFuncAttributeMaxDynamicSharedMemorySize, GEMM_SMEM);

    // idx 0..2: zeroing
    zero_int_kernel<<<(TN+255)/256, 256>>>(cnt, TN);
    zero_int_kernel<<<(TN+255)/256, 256>>>(cursor, TN);
    zero_float_kernel<<<(NN*HH+255)/256, 256>>>(h, NN*HH);

    // idx 3: first big GEMM (ncu profiling window)
    dim3 gL(TN/128, 1);
    gemm_kernel<0><<<gL, 256, GEMM_SMEM>>>(x_seq, W1, nullptr, hs, TN, 128, 128);

    // CSR build + weight transposes
    count_kernel<<<(TE+255)/256, 256>>>(ei, cnt);
    dinv_kernel<<<(TN+255)/256, 256>>>(cnt, dinv);
    scan_kernel<<<T, 1024>>>(cnt, rowptr);
    scatter_kernel<<<(TE+255)/256, 256>>>(ei, rowptr, cursor, col);
    transpose_kernel<<<(384*128+255)/256, 256>>>(w_ih, wihT);
    transpose_kernel<<<(384*128+255)/256, 256>>>(w_hh, whhT);

    // GCN layers
    int aggBlocks = (TN*32 + 255)/256;
    agg_kernel<true ><<<aggBlocks, 256>>>(hs, dinv, rowptr, col, b1, layer);
    gemm_kernel<0><<<gL, 256, GEMM_SMEM>>>(layer, W2, nullptr, hs, TN, 128, 128);
    agg_kernel<true ><<<aggBlocks, 256>>>(hs, dinv, rowptr, col, b2, layer);
    gemm_kernel<0><<<gL, 256, GEMM_SMEM>>>(layer, W3, nullptr, hs, TN, 128, 128);
    agg_kernel<false><<<aggBlocks, 256>>>(hs, dinv, rowptr, col, b3, feats);

    // GRU: batched input gates, sequential hidden chain
    dim3 gGI(TN/128, 3);
    gemm_kernel<1><<<gGI, 256, GEMM_SMEM>>>(feats, wihT, b_ih, gi, TN, 384, 384);

    dim3 gGH((NN+127)/128, 3);
    int gateBlocks = (NN*HH/4 + 255)/256;
    for (int t = 0; t < T; t++) {
        gemm_kernel<1><<<gGH, 256, GEMM_SMEM>>>(h, whhT, b_hh, gh, NN, 384, 384);
        gru_gates_kernel<<<gateBlocks, 256>>>(gi + (size_t)t*NN*3*HH, gh, h);
    }

    decode_kernel<<<(PP*32 + 255)/256, 256>>>(pairs, h, out);
}

// round 8
// speedup vs baseline: 8.8692x; 1.2130x over previous
#include <cuda_runtime.h>
#include <cuda_bf16.h>
#include <math.h>

#define T  16
#define NN 20000
#define EE 320000
#define CC 128
#define HH 128
#define PP 100000
#define TN (T*NN)
#define TE (T*EE)

// ---------------- device scratch ----------------
__device__ float g_hs[TN*HH];           // raw GEMM output h = x@W (gather source)
__device__ float g_layer[TN*HH];        // layer ping buffer
__device__ float g_feats[TN*HH];        // GCN output (GRU input)
__device__ float g_gi[(size_t)TN*3*HH]; // input gates, all steps
__device__ float g_gh[NN*3*HH];         // per-step hidden gates
__device__ float g_h[NN*HH];            // GRU hidden state
__device__ float g_dinv[TN];
__device__ int   g_cnt[TN];
__device__ int   g_cursor[TN];
__device__ int   g_rowptr[T*(NN+1)];
__device__ int   g_col[TE];
// bf16 hi/lo weight images in [n][k] layout with 68-word (136 bf16) padded rows,
// exactly matching the SMEM operand layout (staging = plain copy).
// Layer weights: 1 col-tile = 8704 u32. GRU weights: 3 col-tiles = 26112 u32.
__device__ __align__(16) unsigned int g_W1h[8704],  g_W1l[8704];
__device__ __align__(16) unsigned int g_W2h[8704],  g_W2l[8704];
__device__ __align__(16) unsigned int g_W3h[8704],  g_W3l[8704];
__device__ __align__(16) unsigned int g_wihh[26112], g_wihl[26112];
__device__ __align__(16) unsigned int g_whhh[26112], g_whhl[26112];

// ---------------- utility kernels ----------------
__global__ void zero_int_kernel(int* p, int n) {
    int i = blockIdx.x*blockDim.x + threadIdx.x;
    if (i < n) p[i] = 0;
}
__global__ void zero_float_kernel(float* p, int n) {
    int i = blockIdx.x*blockDim.x + threadIdx.x;
    if (i < n) p[i] = 0.0f;
}

__global__ void count_kernel(const int* __restrict__ ei, int* __restrict__ cnt) {
    int i = blockIdx.x*blockDim.x + threadIdx.x;
    if (i >= TE) return;
    int t = i / EE, e = i - t*EE;
    int dst = ei[(size_t)t*2*EE + EE + e];
    atomicAdd(&cnt[t*NN + dst], 1);
}

__global__ void dinv_kernel(const int* __restrict__ cnt, float* __restrict__ dinv) {
    int i = blockIdx.x*blockDim.x + threadIdx.x;
    if (i >= TN) return;
    dinv[i] = rsqrtf((float)cnt[i] + 1.0f);
}

__global__ void scan_kernel(const int* __restrict__ cnt, int* __restrict__ rowptr) {
    int t = blockIdx.x;
    const int* c = cnt + t*NN;
    int* rp = rowptr + t*(NN+1);
    __shared__ int wsum[32];
    int lane = threadIdx.x & 31;
    int wid  = threadIdx.x >> 5;
    int carry = 0;
    for (int base = 0; base < NN; base += 1024) {
        int i = base + threadIdx.x;
        int v = (i < NN) ? c[i] : 0;
        int inc = v;
        #pragma unroll
        for (int o = 1; o < 32; o <<= 1) {
            int y = __shfl_up_sync(0xffffffffu, inc, o);
            if (lane >= o) inc += y;
        }
        if (lane == 31) wsum[wid] = inc;
        __syncthreads();
        if (wid == 0) {
            int s = wsum[lane];
            #pragma unroll
            for (int o = 1; o < 32; o <<= 1) {
                int y = __shfl_up_sync(0xffffffffu, s, o);
                if (lane >= o) s += y;
            }
            wsum[lane] = s;
        }
        __syncthreads();
        int woff = wid ? wsum[wid-1] : 0;
        if (i < NN) rp[i] = carry + woff + inc - v;
        carry += wsum[31];
        __syncthreads();
    }
    if (threadIdx.x == 0) rp[NN] = carry;
}

__global__ void scatter_kernel(const int* __restrict__ ei, const int* __restrict__ rowptr,
                               int* __restrict__ cursor, int* __restrict__ col) {
    int i = blockIdx.x*blockDim.x + threadIdx.x;
    if (i >= TE) return;
    int t = i / EE, e = i - t*EE;
    int src = ei[(size_t)t*2*EE + e];
    int dst = ei[(size_t)t*2*EE + EE + e];
    int pos = rowptr[t*(NN+1) + dst] + atomicAdd(&cursor[t*NN + dst], 1);
    col[(size_t)t*EE + pos] = src;
}

// ---------------- weight image prep ----------------
// B[n][k] bf16 hi/lo, padded rows of 68 words. transposed=1: W is [K=128][nout]
// (layer weights, B = W^T). transposed=0: W is [nout][128] (GRU weights).
__global__ void prep_weight_kernel(const float* __restrict__ W,
                                   unsigned int* __restrict__ img_h,
                                   unsigned int* __restrict__ img_l,
                                   int nout, int transposed) {
    int idx = blockIdx.x*blockDim.x + threadIdx.x;
    if (idx >= nout*64) return;
    int n = idx >> 6, kp = idx & 63, k0 = kp*2;
    float v0, v1;
    if (transposed) { v0 = W[k0*nout + n]; v1 = W[(k0+1)*nout + n]; }
    else            { v0 = W[n*128 + k0]; v1 = W[n*128 + k0 + 1]; }
    __nv_bfloat16 h0 = __float2bfloat16(v0), h1 = __float2bfloat16(v1);
    float r0 = v0 - __bfloat162float(h0), r1 = v1 - __bfloat162float(h1);
    __nv_bfloat16 l0 = __float2bfloat16(r0), l1 = __float2bfloat16(r1);
    int ct = n >> 7, nl = n & 127;
    int off = ct*8704 + nl*68 + kp;
    img_h[off] = (unsigned int)__bfloat16_as_ushort(h0)
               | ((unsigned int)__bfloat16_as_ushort(h1) << 16);
    img_l[off] = (unsigned int)__bfloat16_as_ushort(l0)
               | ((unsigned int)__bfloat16_as_ushort(l1) << 16);
}

// ---------------- HMMA bf16x3 GEMM ----------------
// C[128-rowblock, ct*128..+128] = A[M,128](fp32 -> bf16 hi/lo) @ B (pre-baked images).
// 256 threads = 8 warps in 2(M)x4(N) grid; warp tile 64x32 via mma.sync.m16n8k16.
// Split: C = Ah*Bh + Ah*Bl + Al*Bh (Al*Bl dropped, ~2^-16).
// SMEM rows padded to 68 words -> all fragment LDS.32 conflict-free.
#define MM_SMEM (4*8704*4)

__device__ __forceinline__ void mma16816(float* c, const unsigned* a, const unsigned* b) {
    asm volatile("mma.sync.aligned.m16n8k16.row.col.f32.bf16.bf16.f32 "
                 "{%0,%1,%2,%3}, {%4,%5,%6,%7}, {%8,%9}, {%0,%1,%2,%3};"
                 : "+f"(c[0]), "+f"(c[1]), "+f"(c[2]), "+f"(c[3])
                 : "r"(a[0]), "r"(a[1]), "r"(a[2]), "r"(a[3]), "r"(b[0]), "r"(b[1]));
}

template<int EPI>  // 0: plain store, 1: + bias[col]
__global__ void __launch_bounds__(256, 1) mgemm_kernel(
    const float* __restrict__ A,
    const unsigned int* __restrict__ Bimg_h, const unsigned int* __restrict__ Bimg_l,
    const float* __restrict__ bias, float* __restrict__ out,
    int M, int ct_count, int ldOut)
{
    extern __shared__ unsigned int smem_u[];
    unsigned int* Ah = smem_u;          // [128][68]
    unsigned int* Al = Ah + 8704;
    unsigned int* Bh = Al + 8704;
    unsigned int* Bl = Bh + 8704;
    int tid  = threadIdx.x;
    int lane = tid & 31, w = tid >> 5;
    int warp_m = w & 1, warp_n = w >> 1;
    int g = lane >> 2, q = lane & 3;
    int row0 = blockIdx.x * 128;

    // ---- stage A: fp32 -> bf16 hi/lo ----
    for (int u = tid; u < 2048; u += 256) {
        int r = u >> 4, kq = u & 15;           // row, word-quad (8 k values)
        int grow = row0 + r;
        float4 va = make_float4(0.f,0.f,0.f,0.f), vb = va;
        if (grow < M) {
            va = *(const float4*)&A[(size_t)grow*128 + kq*8];
            vb = *(const float4*)&A[(size_t)grow*128 + kq*8 + 4];
        }
        float vals[8] = {va.x, va.y, va.z, va.w, vb.x, vb.y, vb.z, vb.w};
        unsigned int hi[4], lo[4];
        #pragma unroll
        for (int j = 0; j < 4; j++) {
            __nv_bfloat16 h0 = __float2bfloat16(vals[2*j]);
            __nv_bfloat16 h1 = __float2bfloat16(vals[2*j+1]);
            float r0 = vals[2*j]   - __bfloat162float(h0);
            float r1 = vals[2*j+1] - __bfloat162float(h1);
            __nv_bfloat16 l0 = __float2bfloat16(r0), l1 = __float2bfloat16(r1);
            hi[j] = (unsigned int)__bfloat16_as_ushort(h0)
                  | ((unsigned int)__bfloat16_as_ushort(h1) << 16);
            lo[j] = (unsigned int)__bfloat16_as_ushort(l0)
                  | ((unsigned int)__bfloat16_as_ushort(l1) << 16);
        }
        *(uint4*)&Ah[r*68 + kq*4] = make_uint4(hi[0], hi[1], hi[2], hi[3]);
        *(uint4*)&Al[r*68 + kq*4] = make_uint4(lo[0], lo[1], lo[2], lo[3]);
    }
    __syncthreads();

    for (int ct = 0; ct < ct_count; ct++) {
        // ---- stage B: plain copy of pre-swizzled images ----
        const uint4* sh = (const uint4*)(Bimg_h + ct*8704);
        const uint4* sl = (const uint4*)(Bimg_l + ct*8704);
        for (int i = tid; i < 2176; i += 256) {
            ((uint4*)Bh)[i] = sh[i];
            ((uint4*)Bl)[i] = sl[i];
        }
        __syncthreads();

        float acc[4][4][4];
        #pragma unroll
        for (int im = 0; im < 4; im++)
            #pragma unroll
            for (int in = 0; in < 4; in++)
                #pragma unroll
                for (int j = 0; j < 4; j++) acc[im][in][j] = 0.f;

        const unsigned int* Abh = Ah + (warp_m*64 + g)*68 + q;
        const unsigned int* Abl = Al + (warp_m*64 + g)*68 + q;
        const unsigned int* Bbh = Bh + (warp_n*32 + g)*68 + q;
        const unsigned int* Bbl = Bl + (warp_n*32 + g)*68 + q;

        #pragma unroll
        for (int ks = 0; ks < 8; ks++) {
            int ko = ks*8;
            unsigned int ah[4][4], al[4][4], bh[4][2], bl[4][2];
            #pragma unroll
            for (int im = 0; im < 4; im++) {
                int ro = im*1088;                    // im*16 rows * 68
                ah[im][0] = Abh[ro + ko];
                ah[im][1] = Abh[ro + 544 + ko];      // +8 rows
                ah[im][2] = Abh[ro + ko + 4];        // k+8
                ah[im][3] = Abh[ro + 544 + ko + 4];
                al[im][0] = Abl[ro + ko];
                al[im][1] = Abl[ro + 544 + ko];
                al[im][2] = Abl[ro + ko + 4];
                al[im][3] = Abl[ro + 544 + ko + 4];
            }
            #pragma unroll
            for (int in = 0; in < 4; in++) {
                int no = in*544;                     // in*8 rows * 68
                bh[in][0] = Bbh[no + ko];
                bh[in][1] = Bbh[no + ko + 4];
                bl[in][0] = Bbl[no + ko];
                bl[in][1] = Bbl[no + ko + 4];
            }
            #pragma unroll
            for (int im = 0; im < 4; im++)
                #pragma unroll
                for (int in = 0; in < 4; in++)
                    mma16816(acc[im][in], ah[im], bh[in]);
            #pragma unroll
            for (int im = 0; im < 4; im++)
                #pragma unroll
                for (int in = 0; in < 4; in++)
                    mma16816(acc[im][in], ah[im], bl[in]);
            #pragma unroll
            for (int im = 0; im < 4; im++)
                #pragma unroll
                for (int in = 0; in < 4; in++)
                    mma16816(acc[im][in], al[im], bh[in]);
        }

        // ---- epilogue: direct float2 stores ----
        #pragma unroll
        for (int in = 0; in < 4; in++) {
            int col = warp_n*32 + in*8 + q*2;
            float2 bb = make_float2(0.f, 0.f);
            if (EPI == 1) bb = *(const float2*)&bias[ct*128 + col];
            #pragma unroll
            for (int im = 0; im < 4; im++) {
                int row = row0 + warp_m*64 + im*16 + g;
                float* op = out + (size_t)row*ldOut + ct*128 + col;
                if (row < M) {
                    float2 v = make_float2(acc[im][in][0] + bb.x, acc[im][in][1] + bb.y);
                    *(float2*)op = v;
                }
                if (row + 8 < M) {
                    float2 v = make_float2(acc[im][in][2] + bb.x, acc[im][in][3] + bb.y);
                    *(float2*)(op + (size_t)8*ldOut) = v;
                }
            }
        }
        __syncthreads();   // all warps done reading B before restage
    }
}

// ---------------- CSR gather aggregation: one warp per (frame, node) ----------------
template<bool RELU>
__global__ void agg_kernel(const float* __restrict__ hs, const float* __restrict__ dinv,
                           const int* __restrict__ rowptr, const int* __restrict__ col,
                           const float* __restrict__ bias, float* __restrict__ out)
{
    int g = blockIdx.x*blockDim.x + threadIdx.x;
    int w = g >> 5;
    if (w >= TN) return;
    int lane = g & 31;
    int t = w / NN, n = w - t*NN;
    const int* rp = rowptr + t*(NN+1);
    int beg = rp[n], end = rp[n+1];
    const int* cols = col + (size_t)t*EE;
    const float* hsf = hs + (size_t)t*NN*HH;
    const float* dvf = dinv + t*NN;
    int off = lane*4;
    float dv = dvf[n];
    float4 hn = *(const float4*)&hsf[n*HH + off];
    float4 acc = make_float4(hn.x*dv, hn.y*dv, hn.z*dv, hn.w*dv);
    int e = beg;
    for (; e + 4 <= end; e += 4) {
        int s0 = cols[e], s1 = cols[e+1], s2 = cols[e+2], s3 = cols[e+3];
        float d0 = dvf[s0], d1 = dvf[s1], d2 = dvf[s2], d3 = dvf[s3];
        float4 v0 = *(const float4*)&hsf[s0*HH + off];
        float4 v1 = *(const float4*)&hsf[s1*HH + off];
        float4 v2 = *(const float4*)&hsf[s2*HH + off];
        float4 v3 = *(const float4*)&hsf[s3*HH + off];
        acc.x = fmaf(v0.x,d0, fmaf(v1.x,d1, fmaf(v2.x,d2, fmaf(v3.x,d3, acc.x))));
        acc.y = fmaf(v0.y,d0, fmaf(v1.y,d1, fmaf(v2.y,d2, fmaf(v3.y,d3, acc.y))));
        acc.z = fmaf(v0.z,d0, fmaf(v1.z,d1, fmaf(v2.z,d2, fmaf(v3.z,d3, acc.z))));
        acc.w = fmaf(v0.w,d0, fmaf(v1.w,d1, fmaf(v2.w,d2, fmaf(v3.w,d3, acc.w))));
    }
    for (; e < end; e++) {
        int s = cols[e];
        float ds = dvf[s];
        float4 vv = *(const float4*)&hsf[s*HH + off];
        acc.x = fmaf(vv.x, ds, acc.x); acc.y = fmaf(vv.y, ds, acc.y);
        acc.z = fmaf(vv.z, ds, acc.z); acc.w = fmaf(vv.w, ds, acc.w);
    }
    float4 bb = *(const float4*)&bias[off];
    float4 o;
    o.x = fmaf(acc.x, dv, bb.x);
    o.y = fmaf(acc.y, dv, bb.y);
    o.z = fmaf(acc.z, dv, bb.z);
    o.w = fmaf(acc.w, dv, bb.w);
    if (RELU) {
        o.x = fmaxf(o.x, 0.f); o.y = fmaxf(o.y, 0.f);
        o.z = fmaxf(o.z, 0.f); o.w = fmaxf(o.w, 0.f);
    }
    *(float4*)&out[(size_t)w*HH + off] = o;
}

// ---------------- GRU gate fusion ----------------
__global__ void gru_gates_kernel(const float* __restrict__ gi, const float* __restrict__ gh,
                                 float* __restrict__ h)
{
    int idx = blockIdx.x*blockDim.x + threadIdx.x;
    if (idx >= NN*HH/4) return;
    int n  = idx >> 5;
    int j4 = (idx & 31) * 4;
    const float* gir = gi + (size_t)n*384;
    const float* ghr = gh + (size_t)n*384;
    float4 ir  = *(const float4*)&gir[j4];
    float4 iz  = *(const float4*)&gir[128 + j4];
    float4 inn = *(const float4*)&gir[256 + j4];
    float4 hr  = *(const float4*)&ghr[j4];
    float4 hz  = *(const float4*)&ghr[128 + j4];
    float4 hn  = *(const float4*)&ghr[256 + j4];
    float4 hp  = *(const float4*)&h[(size_t)n*HH + j4];
    float4 o;
    #define GATE(c) { \
        float rr = 1.f/(1.f+__expf(-(ir.c + hr.c))); \
        float zz = 1.f/(1.f+__expf(-(iz.c + hz.c))); \
        float nn2 = tanhf(inn.c + rr*hn.c); \
        o.c = (1.f - zz)*nn2 + zz*hp.c; }
    GATE(x) GATE(y) GATE(z) GATE(w)
    #undef GATE
    *(float4*)&h[(size_t)n*HH + j4] = o;
}

// ---------------- decode ----------------
__global__ void decode_kernel(const int* __restrict__ pairs, const float* __restrict__ h,
                              float* __restrict__ out)
{
    int g = blockIdx.x*blockDim.x + threadIdx.x;
    int w = g >> 5;
    if (w >= PP) return;
    int lane = g & 31;
    int s = pairs[w], d = pairs[PP + w];
    float4 a = *(const float4*)&h[(size_t)s*HH + lane*4];
    float4 b = *(const float4*)&h[(size_t)d*HH + lane*4];
    float sum = a.x*b.x + a.y*b.y + a.z*b.z + a.w*b.w;
    #pragma unroll
    for (int o = 16; o; o >>= 1) sum += __shfl_xor_sync(0xffffffffu, sum, o);
    if (lane == 0) out[w] = sum;
}

// ---------------- launch ----------------
extern "C" void kernel_launch(void* const* d_in, const int* in_sizes, int n_in,
                              void* d_out, int out_size)
{
    const float* x_seq = (const float*)d_in[0];
    const int*   ei    = (const int*)d_in[1];
    const int*   pairs = (const int*)d_in[2];
    const float* W1 = (const float*)d_in[3];
    const float* b1 = (const float*)d_in[4];
    const float* W2 = (const float*)d_in[5];
    const float* b2 = (const float*)d_in[6];
    const float* W3 = (const float*)d_in[7];
    const float* b3 = (const float*)d_in[8];
    const float* w_ih = (const float*)d_in[9];
    const float* w_hh = (const float*)d_in[10];
    const float* b_ih = (const float*)d_in[11];
    const float* b_hh = (const float*)d_in[12];
    float* out = (float*)d_out;
    (void)in_sizes; (void)n_in; (void)out_size;

    void* p;
    float *hs, *layer, *feats, *gi, *gh, *h, *dinv;
    int *cnt, *cursor, *rowptr, *col;
    unsigned int *W1h,*W1l,*W2h,*W2l,*W3h,*W3l,*wihh,*wihl,*whhh,*whhl;
    cudaGetSymbolAddress(&p, g_hs);     hs     = (float*)p;
    cudaGetSymbolAddress(&p, g_layer);  layer  = (float*)p;
    cudaGetSymbolAddress(&p, g_feats);  feats  = (float*)p;
    cudaGetSymbolAddress(&p, g_gi);     gi     = (float*)p;
    cudaGetSymbolAddress(&p, g_gh);     gh     = (float*)p;
    cudaGetSymbolAddress(&p, g_h);      h      = (float*)p;
    cudaGetSymbolAddress(&p, g_dinv);   dinv   = (float*)p;
    cudaGetSymbolAddress(&p, g_cnt);    cnt    = (int*)p;
    cudaGetSymbolAddress(&p, g_cursor); cursor = (int*)p;
    cudaGetSymbolAddress(&p, g_rowptr); rowptr = (int*)p;
    cudaGetSymbolAddress(&p, g_col);    col    = (int*)p;
    cudaGetSymbolAddress(&p, g_W1h);  W1h  = (unsigned int*)p;
    cudaGetSymbolAddress(&p, g_W1l);  W1l  = (unsigned int*)p;
    cudaGetSymbolAddress(&p, g_W2h);  W2h  = (unsigned int*)p;
    cudaGetSymbolAddress(&p, g_W2l);  W2l  = (unsigned int*)p;
    cudaGetSymbolAddress(&p, g_W3h);  W3h  = (unsigned int*)p;
    cudaGetSymbolAddress(&p, g_W3l);  W3l  = (unsigned int*)p;
    cudaGetSymbolAddress(&p, g_wihh); wihh = (unsigned int*)p;
    cudaGetSymbolAddress(&p, g_wihl); wihl = (unsigned int*)p;
    cudaGetSymbolAddress(&p, g_whhh); whhh = (unsigned int*)p;
    cudaGetSymbolAddress(&p, g_whhl); whhl = (unsigned int*)p;

    cudaFuncSetAttribute(mgemm_kernel<0>, cudaFuncAttributeMaxDynamicSharedMemorySize, MM_SMEM);
    cudaFuncSetAttribute(mgemm_kernel<1>, cudaFuncAttributeMaxDynamicSharedMemorySize, MM_SMEM);

    // idx 0..2: zeroing
    zero_int_kernel<<<(TN+255)/256, 256>>>(cnt, TN);
    zero_int_kernel<<<(TN+255)/256, 256>>>(cursor, TN);
    zero_float_kernel<<<(NN*HH+255)/256, 256>>>(h, NN*HH);

    // idx 3..4: W1/W2 prep (layer weights are [K][N] -> transposed=1)
    prep_weight_kernel<<<(128*64+255)/256, 256>>>(W1, W1h, W1l, 128, 1);
    prep_weight_kernel<<<(128*64+255)/256, 256>>>(W2, W2h, W2l, 128, 1);

    // idx 5: first big tensor GEMM (ncu -s 5 profiling window)
    mgemm_kernel<0><<<TN/128, 256, MM_SMEM>>>(x_seq, W1h, W1l, nullptr, hs, TN, 1, 128);

    // remaining preps + CSR build
    prep_weight_kernel<<<(128*64+255)/256, 256>>>(W3, W3h, W3l, 128, 1);
    prep_weight_kernel<<<(384*64+255)/256, 256>>>(w_ih, wihh, wihl, 384, 0);
    prep_weight_kernel<<<(384*64+255)/256, 256>>>(w_hh, whhh, whhl, 384, 0);
    count_kernel<<<(TE+255)/256, 256>>>(ei, cnt);
    dinv_kernel<<<(TN+255)/256, 256>>>(cnt, dinv);
    scan_kernel<<<T, 1024>>>(cnt, rowptr);
    scatter_kernel<<<(TE+255)/256, 256>>>(ei, rowptr, cursor, col);

    // GCN layers
    int aggBlocks = (TN*32 + 255)/256;
    agg_kernel<true ><<<aggBlocks, 256>>>(hs, dinv, rowptr, col, b1, layer);
    mgemm_kernel<0><<<TN/128, 256, MM_SMEM>>>(layer, W2h, W2l, nullptr, hs, TN, 1, 128);
    agg_kernel<true ><<<aggBlocks, 256>>>(hs, dinv, rowptr, col, b2, layer);
    mgemm_kernel<0><<<TN/128, 256, MM_SMEM>>>(layer, W3h, W3l, nullptr, hs, TN, 1, 128);
    agg_kernel<false><<<aggBlocks, 256>>>(hs, dinv, rowptr, col, b3, feats);

    // GRU: batched input gates (A staged once per block, 3 col-tiles)
    mgemm_kernel<1><<<TN/128, 256, MM_SMEM>>>(feats, wihh, wihl, b_ih, gi, TN, 3, 384);

    int ghBlocks = (NN+127)/128;
    int gateBlocks = (NN*HH/4 + 255)/256;
    for (int t = 0; t < T; t++) {
        mgemm_kernel<1><<<ghBlocks, 256, MM_SMEM>>>(h, whhh, whhl, b_hh, gh, NN, 3, 384);
        gru_gates_kernel<<<gateBlocks, 256>>>(gi + (size_t)t*NN*3*HH, gh, h);
    }

    decode_kernel<<<(PP*32 + 255)/256, 256>>>(pairs, h, out);
}